// round 9
// baseline (speedup 1.0000x reference)
#include <cuda_runtime.h>

// LIF membrane recurrence, HBM-bound streaming kernel.
//   mem[t] = 0.25 * mem[t-1] * (1 - spike[t-1]) + x[t] ; spike[t] = mem[t] > 0.5
// x: (8, 32, 128, 32, 32) fp32. 134 MB read + 134 MB write, zero reuse.
//
// History (kernel time): R0/R3/R6/R7 float4 baseline 36.1-36.7us, DRAM ~75%.
//   .cs/.cg hints -> +8.7us; sw pipeline -> +2us; tile x2 / block 512 neutral.
// R8: last untested axis — Blackwell 256-bit vector ld/st (ld/st.global.v8.b32,
// SASS LDG.E.256/STG.E.256). Halves LSU issue + L1tex wavefronts per byte.
// Each thread: 8 contiguous floats per timestep (32B-aligned), front-batch
// all 8 timesteps (MLP=8 x 256-bit).

#define T_STEPS 8
#define INNER   (32 * 128 * 32 * 32)   // 4,194,304 elements per timestep
#define VEC     8                       // floats per thread per timestep
#define NTHREADS_TOTAL (INNER / VEC)    // 524,288

__global__ void lif_kernel(const float* __restrict__ x, float* __restrict__ out) {
    size_t base = ((size_t)blockIdx.x * blockDim.x + threadIdx.x) * VEC;

    // Front-batch all 8 timestep loads as 256-bit vectors.
    unsigned v[T_STEPS][VEC];
#pragma unroll
    for (int t = 0; t < T_STEPS; ++t) {
        const float* p = x + (size_t)t * INNER + base;
        asm volatile(
            "ld.global.v8.b32 {%0,%1,%2,%3,%4,%5,%6,%7}, [%8];"
            : "=r"(v[t][0]), "=r"(v[t][1]), "=r"(v[t][2]), "=r"(v[t][3]),
              "=r"(v[t][4]), "=r"(v[t][5]), "=r"(v[t][6]), "=r"(v[t][7])
            : "l"(p));
    }

    const float DECAY = 0.25f;
    const float THR   = 0.5f;

    float m[VEC] = {};
    float s[VEC] = {};

#pragma unroll
    for (int t = 0; t < T_STEPS; ++t) {
        unsigned o[VEC];
#pragma unroll
        for (int j = 0; j < VEC; ++j) {
            m[j] = DECAY * m[j] * (1.0f - s[j]) + __uint_as_float(v[t][j]);
            s[j] = (m[j] > THR) ? 1.0f : 0.0f;
            o[j] = __float_as_uint(s[j]);
        }
        float* q = out + (size_t)t * INNER + base;
        asm volatile(
            "st.global.v8.b32 [%0], {%1,%2,%3,%4,%5,%6,%7,%8};"
            :: "l"(q),
               "r"(o[0]), "r"(o[1]), "r"(o[2]), "r"(o[3]),
               "r"(o[4]), "r"(o[5]), "r"(o[6]), "r"(o[7])
            : "memory");
    }
}

extern "C" void kernel_launch(void* const* d_in, const int* in_sizes, int n_in,
                              void* d_out, int out_size) {
    const float* x = (const float*)d_in[0];
    float* out = (float*)d_out;
    int threads = 256;
    int blocks = NTHREADS_TOTAL / threads;   // 2048, exact
    lif_kernel<<<blocks, threads>>>(x, out);
}

// round 10
// speedup vs baseline: 1.0613x; 1.0613x over previous
#include <cuda_runtime.h>

// LIF membrane recurrence — FINAL (committed floor).
//   mem[0] = x[0]; mem[t] = 0.25 * mem[t-1] * (1 - spike[t-1]) + x[t]
//   spike[t] = (mem[t] > 0.5)
// x: (8, 32, 128, 32, 32) fp32. Recurrence only along t; 4,194,304 independent
// sites. 134 MB read + 134 MB write, zero reuse -> pure HBM-bound.
//
// Session search matrix (kernel time, all axes tested in isolation):
//   plain float4, front-batch 8, 256thr : 36.1-36.7us, DRAM 75%  << FLOOR
//   .cs ld+st / .cg loads               : 44.7 / 45.3us (L2 buffering is load-bearing)
//   sw pipeline (MLP 8->2)              : 38.1us (issue overhead)
//   tile x2 / block 512                 : 37.2 / 36.1us (neutral)
//   v8.b32 256-bit ld/st                : 41.9us (76 regs -> occ 29%)
// Effective DRAM throughput incl. deferred L2 writeback ~7.4 TB/s: saturated.
// Compute pipes <9%, tensor 0% — no non-memory lever exists for this op.

#define T_STEPS 8
#define INNER   (32 * 128 * 32 * 32)   // 4,194,304 elements per timestep
#define INNER4  (INNER / 4)            // 1,048,576 float4 sites

__global__ void lif_kernel(const float4* __restrict__ x, float4* __restrict__ out) {
    int i = blockIdx.x * blockDim.x + threadIdx.x;
    if (i >= INNER4) return;

    // Front-batch all 8 timestep loads (independent -> MLP=8).
    float4 xv[T_STEPS];
#pragma unroll
    for (int t = 0; t < T_STEPS; ++t) {
        xv[t] = x[(size_t)t * INNER4 + i];
    }

    const float DECAY = 0.25f;
    const float THR   = 0.5f;

    float m0 = 0.f, m1 = 0.f, m2 = 0.f, m3 = 0.f;
    float s0 = 0.f, s1 = 0.f, s2 = 0.f, s3 = 0.f;

#pragma unroll
    for (int t = 0; t < T_STEPS; ++t) {
        m0 = DECAY * m0 * (1.0f - s0) + xv[t].x;
        m1 = DECAY * m1 * (1.0f - s1) + xv[t].y;
        m2 = DECAY * m2 * (1.0f - s2) + xv[t].z;
        m3 = DECAY * m3 * (1.0f - s3) + xv[t].w;
        s0 = (m0 > THR) ? 1.0f : 0.0f;
        s1 = (m1 > THR) ? 1.0f : 0.0f;
        s2 = (m2 > THR) ? 1.0f : 0.0f;
        s3 = (m3 > THR) ? 1.0f : 0.0f;
        out[(size_t)t * INNER4 + i] = make_float4(s0, s1, s2, s3);
    }
}

extern "C" void kernel_launch(void* const* d_in, const int* in_sizes, int n_in,
                              void* d_out, int out_size) {
    const float4* x = (const float4*)d_in[0];
    float4* out = (float4*)d_out;
    int threads = 256;
    int blocks = (INNER4 + threads - 1) / threads;   // 4096
    lif_kernel<<<blocks, threads>>>(x, out);
}